// round 5
// baseline (speedup 1.0000x reference)
#include <cuda_runtime.h>
#include <cuda_bf16.h>
#include <math.h>

#define NN 50000
#define EE 800000
#define EA 850000   // EE + NN self loops
#define HC 128
#define HEADS 4
#define SLOPE 0.2f
#define SCAN_B 200  // scan blocks (200*256 = 51200 >= NN)

// ---------------- scratch (device globals; no allocation allowed) ----------------
__device__ __align__(16) float g_h[2][NN * HC];     // ping-pong node features
__device__ __align__(16) float g_xl[NN * HC];
__device__ __align__(16) float g_xr[NN * HC];
__device__ __align__(16) int   g_src[EA];
__device__ __align__(16) int   g_dst[EA];
__device__ __align__(16) int   g_csr[EA];           // src ids grouped by dst
__device__ __align__(16) int   g_off[NN + 1];       // CSR offsets
__device__ __align__(16) int   g_cnt[NN];           // zero-init at load; re-zeroed by k_scatter
__device__ __align__(16) int   g_cur[NN];
__device__ __align__(16) int   g_bsum[256];
__device__ __align__(16) int   g_boff[256];
__device__ __align__(16) float g_mlp[NN * 16];      // final 16-dim node features
__device__ __align__(16) float g_p1[NN * 6];        // h_mlp @ W3[0:16]
__device__ __align__(16) float g_p2[NN * 6];        // h_mlp @ W3[16:32]

static inline int cdiv(int a, int b) { return (a + b - 1) / b; }

__device__ __forceinline__ void fma2(unsigned long long& d,
                                     unsigned long long a,
                                     unsigned long long b) {
    asm("fma.rn.f32x2 %0, %1, %2, %0;" : "+l"(d) : "l"(a), "l"(b));
}

// ---------------- edge prep: -> int32, self loops, dst histogram ----------------
// dtype detection inline (int64 edge_index has zero high words).
// g_cnt is all-zero on entry: zero-initialized at module load, and re-zeroed by
// k_scatter at the end of every kernel_launch invocation.
__global__ void k_prep(const void* __restrict__ ei) {
    __shared__ int s64;
    if (threadIdx.x == 0) {
        const unsigned int* p = (const unsigned int*)ei;
        s64 = ((p[1] | p[3] | p[5] | p[7]) == 0u) ? 1 : 0;
    }
    __syncthreads();
    int is64 = s64;
    int i = blockIdx.x * blockDim.x + threadIdx.x;
    if (i >= EA) return;
    int s, d;
    if (i < EE) {
        if (is64) {
            const long long* p = (const long long*)ei;
            s = (int)p[i];
            d = (int)p[EE + i];
        } else {
            const int* p = (const int*)ei;
            s = p[i];
            d = p[EE + i];
        }
    } else {
        s = i - EE;
        d = i - EE;
    }
    g_src[i] = s;
    g_dst[i] = d;
    atomicAdd(&g_cnt[d], 1);
}

// ---------------- decoupled scan: phase 1 (block sums) --------------------------
__global__ void __launch_bounds__(256) k_bsum() {
    int t = threadIdx.x, b = blockIdx.x;
    int i = b * 256 + t;
    int v = (i < NN) ? g_cnt[i] : 0;
    #pragma unroll
    for (int off = 16; off >= 1; off >>= 1)
        v += __shfl_xor_sync(0xffffffffu, v, off);
    __shared__ int ws[8];
    if ((t & 31) == 0) ws[t >> 5] = v;
    __syncthreads();
    if (t == 0) {
        int s = 0;
        #pragma unroll
        for (int w = 0; w < 8; w++) s += ws[w];
        g_bsum[b] = s;
    }
}

// ---------------- phase 2: exclusive scan of 200 block sums (1 block) -----------
__global__ void __launch_bounds__(256) k_bscan() {
    int t = threadIdx.x;
    int lane = t & 31, wid = t >> 5;
    int val = (t < SCAN_B) ? g_bsum[t] : 0;
    int v = val;
    #pragma unroll
    for (int off = 1; off < 32; off <<= 1) {
        int u = __shfl_up_sync(0xffffffffu, v, off);
        if (lane >= off) v += u;
    }
    __shared__ int ws[8];
    if (lane == 31) ws[wid] = v;
    __syncthreads();
    if (wid == 0) {
        int s = (lane < 8) ? ws[lane] : 0;
        #pragma unroll
        for (int off = 1; off < 8; off <<= 1) {
            int u = __shfl_up_sync(0xffffffffu, s, off);
            if (lane >= off) s += u;
        }
        if (lane < 8) ws[lane] = s;
    }
    __syncthreads();
    int base = (wid > 0) ? ws[wid - 1] : 0;
    g_boff[t] = base + v - val;   // exclusive
    if (t == 0) g_off[NN] = EA;
}

// ---------------- phase 3: local scan + global offset ---------------------------
__global__ void __launch_bounds__(256) k_offs() {
    int t = threadIdx.x, b = blockIdx.x;
    int i = b * 256 + t;
    int lane = t & 31, wid = t >> 5;
    int val = (i < NN) ? g_cnt[i] : 0;
    int v = val;
    #pragma unroll
    for (int off = 1; off < 32; off <<= 1) {
        int u = __shfl_up_sync(0xffffffffu, v, off);
        if (lane >= off) v += u;
    }
    __shared__ int ws[8];
    if (lane == 31) ws[wid] = v;
    __syncthreads();
    if (wid == 0) {
        int s = (lane < 8) ? ws[lane] : 0;
        #pragma unroll
        for (int off = 1; off < 8; off <<= 1) {
            int u = __shfl_up_sync(0xffffffffu, s, off);
            if (lane >= off) s += u;
        }
        if (lane < 8) ws[lane] = s;
    }
    __syncthreads();
    int base = ((wid > 0) ? ws[wid - 1] : 0) + g_boff[b];
    if (i < NN) {
        int excl = base + v - val;
        g_off[i] = excl;
        g_cur[i] = excl;
    }
}

// scatter + re-zero g_cnt for the next kernel_launch invocation
__global__ void k_scatter() {
    int i = blockIdx.x * blockDim.x + threadIdx.x;
    if (i < NN) g_cnt[i] = 0;
    if (i >= EA) return;
    int pos = atomicAdd(&g_cur[g_dst[i]], 1);
    g_csr[pos] = g_src[i];
}

// ---------------- xl = h@Wl+bl, xr = h@Wr+br; packed f32x2 FMA -------------------
__global__ void __launch_bounds__(256) k_gemm(const float* __restrict__ hin,
                                              const float* __restrict__ Wl,
                                              const float* __restrict__ Wr,
                                              const float* __restrict__ bl,
                                              const float* __restrict__ br) {
    __shared__ float4 sh[32][32];   // 32 nodes x 128 floats
    int t = threadIdx.x;
    int nb = blockIdx.x * 32;
    const float4* hin4 = (const float4*)hin;
    #pragma unroll
    for (int r = 0; r < 4; r++) {
        int p = r * 256 + t;        // 0..1023
        int n = p >> 5, k4 = p & 31;
        int gn = nb + n;
        float4 v = make_float4(0.f, 0.f, 0.f, 0.f);
        if (gn < NN) v = hin4[(size_t)gn * 32 + k4];
        sh[n][k4] = v;
    }
    __syncthreads();

    int col = t & 127;
    const float* W = (t < 128) ? Wl : Wr;
    float* outp    = (t < 128) ? g_xl : g_xr;
    float bias     = (t < 128) ? bl[col] : br[col];

    unsigned long long acc[32];
    #pragma unroll
    for (int n = 0; n < 32; n++) acc[n] = 0ull;

    #pragma unroll 2
    for (int k4 = 0; k4 < 32; k4++) {
        float w0 = W[(k4 * 4 + 0) * 128 + col];
        float w1 = W[(k4 * 4 + 1) * 128 + col];
        float w2 = W[(k4 * 4 + 2) * 128 + col];
        float w3 = W[(k4 * 4 + 3) * 128 + col];
        unsigned long long wp01, wp23;
        asm("mov.b64 %0, {%1, %2};" : "=l"(wp01) : "f"(w0), "f"(w1));
        asm("mov.b64 %0, {%1, %2};" : "=l"(wp23) : "f"(w2), "f"(w3));
        #pragma unroll
        for (int n = 0; n < 32; n++) {
            ulonglong2 hv = *(const ulonglong2*)&sh[n][k4];
            fma2(acc[n], hv.x, wp01);   // k0,k1 partials
            fma2(acc[n], hv.y, wp23);   // k2,k3 partials
        }
    }
    #pragma unroll
    for (int n = 0; n < 32; n++) {
        int gn = nb + n;
        if (gn < NN) {
            float lo, hi;
            asm("mov.b64 {%0, %1}, %2;" : "=f"(lo), "=f"(hi) : "l"(acc[n]));
            outp[(size_t)gn * 128 + col] = lo + hi + bias;
        }
    }
}

// ---------------- fused edge pass: online softmax + aggregate + bias + relu -----
// one warp per destination node; csr index prefetched 2 ahead, row 1 ahead
__global__ void __launch_bounds__(256) k_edge(const float* __restrict__ att,
                                              const float* __restrict__ cb,
                                              float* __restrict__ hnext) {
    int gid = blockIdx.x * blockDim.x + threadIdx.x;
    int n = gid >> 5, lane = gid & 31;
    if (n >= NN) return;
    const float4* xl4 = (const float4*)g_xl;
    float4 xr = ((const float4*)g_xr)[(size_t)n * 32 + lane];
    float4 w  = ((const float4*)att)[lane];
    int beg = g_off[n], end = g_off[n + 1];
    int cnt = end - beg;                   // >= 1 (self loop guaranteed)

    // prefetch pipeline: idx 2 ahead, row 1 ahead
    int   src0 = g_csr[beg];
    float4 an  = xl4[(size_t)src0 * 32 + lane];          // row for i=0
    int   idx1 = (cnt > 1) ? g_csr[beg + 1] : 0;         // idx for i=1

    float m = -1e30f, s = 0.f;
    float4 acc = make_float4(0.f, 0.f, 0.f, 0.f);

    for (int i = 0; i < cnt; i++) {
        float4 a = an;
        if (i + 1 < cnt) {
            an = xl4[(size_t)idx1 * 32 + lane];          // issue early
            idx1 = (i + 2 < cnt) ? g_csr[beg + i + 2] : 0;
        }
        float vx = a.x + xr.x, vy = a.y + xr.y, vz = a.z + xr.z, vw = a.w + xr.w;
        vx = fmaxf(vx, SLOPE * vx);
        vy = fmaxf(vy, SLOPE * vy);
        vz = fmaxf(vz, SLOPE * vz);
        vw = fmaxf(vw, SLOPE * vw);
        float p = vx * w.x + vy * w.y + vz * w.z + vw * w.w;
        p += __shfl_xor_sync(0xffffffffu, p, 1);
        p += __shfl_xor_sync(0xffffffffu, p, 2);
        p += __shfl_xor_sync(0xffffffffu, p, 4);   // per-head score, all 8 lanes
        float mn = fmaxf(m, p);
        float scale = __expf(m - mn);
        float t = __expf(p - mn);
        s = s * scale + t;
        acc.x = acc.x * scale + t * a.x;
        acc.y = acc.y * scale + t * a.y;
        acc.z = acc.z * scale + t * a.z;
        acc.w = acc.w * scale + t * a.w;
        m = mn;
    }
    float inv = __fdividef(1.f, s + 1e-16f);
    float4 cbv = ((const float4*)cb)[lane];
    float4 o;
    o.x = fmaxf(fmaf(acc.x, inv, cbv.x), 0.f);
    o.y = fmaxf(fmaf(acc.y, inv, cbv.y), 0.f);
    o.z = fmaxf(fmaf(acc.z, inv, cbv.z), 0.f);
    o.w = fmaxf(fmaf(acc.w, inv, cbv.w), 0.f);
    ((float4*)hnext)[(size_t)n * 32 + lane] = o;
}

// ---------------- fused MLP: relu(h@W1+b1) -> relu(@W2+b2) -> W3 partials -------
__global__ void __launch_bounds__(128) k_mlp(const float* __restrict__ hin,
                                             const float* __restrict__ W1,
                                             const float* __restrict__ b1,
                                             const float* __restrict__ W2,
                                             const float* __restrict__ b2,
                                             const float* __restrict__ W3) {
    __shared__ float4 sh[16][32];
    __shared__ float  s1[16][33];
    __shared__ float  s2[16][17];
    int t = threadIdx.x;
    int nb = blockIdx.x * 16;       // NN % 16 == 0
    const float4* hin4 = (const float4*)hin;
    #pragma unroll
    for (int r = 0; r < 4; r++) {
        int p = r * 128 + t;        // 0..511
        int n = p >> 5, k4 = p & 31;
        sh[n][k4] = hin4[(size_t)(nb + n) * 32 + k4];
    }
    __syncthreads();
    {
        int c = t & 31, n0 = t >> 5;
        #pragma unroll
        for (int rep = 0; rep < 4; rep++) {
            int n = n0 + rep * 4;
            float acc = b1[c];
            #pragma unroll 8
            for (int k4 = 0; k4 < 32; k4++) {
                float4 h = sh[n][k4];
                acc = fmaf(h.x, W1[(k4 * 4 + 0) * 32 + c], acc);
                acc = fmaf(h.y, W1[(k4 * 4 + 1) * 32 + c], acc);
                acc = fmaf(h.z, W1[(k4 * 4 + 2) * 32 + c], acc);
                acc = fmaf(h.w, W1[(k4 * 4 + 3) * 32 + c], acc);
            }
            s1[n][c] = fmaxf(acc, 0.f);
        }
    }
    __syncthreads();
    {
        int c = t & 15, n0 = t >> 4;
        #pragma unroll
        for (int rep = 0; rep < 2; rep++) {
            int n = n0 + rep * 8;
            float acc = b2[c];
            #pragma unroll
            for (int k = 0; k < 32; k++)
                acc = fmaf(s1[n][k], W2[k * 16 + c], acc);
            float v = fmaxf(acc, 0.f);
            s2[n][c] = v;
            g_mlp[(size_t)(nb + n) * 16 + c] = v;
        }
    }
    __syncthreads();
    // p1/p2: 16 nodes x 6 cols = 96 outputs, threads 0..95
    if (t < 96) {
        int n = t / 6, c = t - (t / 6) * 6;
        float a1 = 0.f, a2 = 0.f;
        #pragma unroll
        for (int k = 0; k < 16; k++) {
            float v = s2[n][k];
            a1 = fmaf(v, W3[k * 6 + c], a1);
            a2 = fmaf(v, W3[(16 + k) * 6 + c], a2);
        }
        g_p1[(nb + n) * 6 + c] = a1;
        g_p2[(nb + n) * 6 + c] = a2;
    }
}

// ---------------- edge head: e = concat(h[src], h[dst]); out = p1+p2+b3 ---------
__global__ void __launch_bounds__(256) k_eout(const float* __restrict__ b3,
                                              float* __restrict__ outp,
                                              float* __restrict__ eoutp) {
    int gid = blockIdx.x * blockDim.x + threadIdx.x;
    int e = gid >> 5, lane = gid & 31;
    if (e >= EE) return;
    int s = g_src[e], d = g_dst[e];
    int node = (lane < 16) ? s : d;
    float v = g_mlp[(size_t)node * 16 + (lane & 15)];
    eoutp[(size_t)e * 32 + lane] = v;
    if (lane < 6) {
        float o = g_p1[s * 6 + lane] + g_p2[d * 6 + lane] + b3[lane];
        outp[(size_t)e * 6 + lane] = o;
    }
}

// ---------------- launch ---------------------------------------------------------
extern "C" void kernel_launch(void* const* d_in, const int* in_sizes, int n_in,
                              void* d_out, int out_size) {
    const float* x   = (const float*)d_in[0];
    const void*  ei  = d_in[1];
    // d_in[2] = batch (unused)
    const float* Wl  = (const float*)d_in[3];
    const float* Wr  = (const float*)d_in[4];
    const float* bl  = (const float*)d_in[5];
    const float* br  = (const float*)d_in[6];
    const float* att = (const float*)d_in[7];
    const float* cb  = (const float*)d_in[8];
    const float* W1  = (const float*)d_in[9];
    const float* b1  = (const float*)d_in[10];
    const float* W2  = (const float*)d_in[11];
    const float* b2  = (const float*)d_in[12];
    const float* W3  = (const float*)d_in[13];
    const float* b3  = (const float*)d_in[14];

    float* outp  = (float*)d_out;                   // [E, 6]
    float* eoutp = outp + (size_t)EE * 6;           // [E, 32]

    void* hsym = nullptr;
    cudaGetSymbolAddress(&hsym, g_h);
    float* hb0 = (float*)hsym;
    float* hb1 = hb0 + (size_t)NN * HC;

    // launch order: k_gemm (layer 0) deliberately placed 4th for ncu capture
    k_prep<<<cdiv(EA, 256), 256>>>(ei);                             // 1
    k_bsum<<<SCAN_B, 256>>>();                                      // 2
    k_bscan<<<1, 256>>>();                                          // 3
    k_gemm<<<cdiv(NN, 32), 256>>>(x, Wl, Wr, bl, br);               // 4 (profiled)
    k_offs<<<SCAN_B, 256>>>();                                      // 5
    k_scatter<<<cdiv(EA, 256), 256>>>();                            // 6

    float* hbuf[3] = {hb0, hb1, hb0};
    const float* hin = x;
    for (int i = 0; i < 3; i++) {
        float* hnext = hbuf[i];
        if (i > 0)
            k_gemm<<<cdiv(NN, 32), 256>>>(hin,
                                          Wl + (size_t)i * 128 * 128,
                                          Wr + (size_t)i * 128 * 128,
                                          bl + (size_t)i * 128,
                                          br + (size_t)i * 128);
        k_edge<<<cdiv(NN * 32, 256), 256>>>(att + (size_t)i * 128,
                                            cb + (size_t)i * 128, hnext);
        hin = hnext;
    }

    k_mlp<<<NN / 16, 128>>>(hin, W1, b1, W2, b2, W3);
    k_eout<<<cdiv(EE * 32, 256), 256>>>(b3, outp, eoutp);
}

// round 6
// speedup vs baseline: 1.2267x; 1.2267x over previous
#include <cuda_runtime.h>
#include <cuda_bf16.h>
#include <math.h>

#define NN 50000
#define EE 800000
#define EA 850000   // EE + NN self loops
#define HC 128
#define HEADS 4
#define SLOPE 0.2f
#define SCAN_B 200  // scan blocks (200*256 = 51200 >= NN)

// ---------------- scratch (device globals; no allocation allowed) ----------------
__device__ __align__(16) float g_h[2][NN * HC];     // ping-pong node features
__device__ __align__(16) float g_xl[NN * HC];
__device__ __align__(16) float g_xr[NN * HC];
__device__ __align__(16) int   g_src[EA];
__device__ __align__(16) int   g_dst[EA];
__device__ __align__(16) int   g_csr[EA];           // src ids grouped by dst
__device__ __align__(16) int   g_off[NN + 1];       // CSR offsets
__device__ __align__(16) int   g_cnt[NN];           // zero-init at load; re-zeroed by k_scatter
__device__ __align__(16) int   g_cur[NN];
__device__ __align__(16) int   g_bsum[256];
__device__ __align__(16) int   g_boff[256];
__device__ __align__(16) float g_mlp[NN * 16];      // final 16-dim node features
__device__ __align__(16) float g_p1[NN * 6];        // h_mlp @ W3[0:16]
__device__ __align__(16) float g_p2[NN * 6];        // h_mlp @ W3[16:32]

static inline int cdiv(int a, int b) { return (a + b - 1) / b; }

__device__ __forceinline__ void fma2(unsigned long long& d,
                                     unsigned long long a,
                                     unsigned long long b) {
    asm("fma.rn.f32x2 %0, %1, %2, %0;" : "+l"(d) : "l"(a), "l"(b));
}
__device__ __forceinline__ unsigned long long rep2(float v) {
    unsigned long long r;
    asm("mov.b64 %0, {%1, %1};" : "=l"(r) : "f"(v));
    return r;
}
__device__ __forceinline__ float2 unpack2(unsigned long long v) {
    float2 r;
    asm("mov.b64 {%0, %1}, %2;" : "=f"(r.x), "=f"(r.y) : "l"(v));
    return r;
}

// ---------------- edge prep: -> int32, self loops, dst histogram ----------------
__global__ void k_prep(const void* __restrict__ ei) {
    __shared__ int s64;
    if (threadIdx.x == 0) {
        const unsigned int* p = (const unsigned int*)ei;
        s64 = ((p[1] | p[3] | p[5] | p[7]) == 0u) ? 1 : 0;
    }
    __syncthreads();
    int is64 = s64;
    int i = blockIdx.x * blockDim.x + threadIdx.x;
    if (i >= EA) return;
    int s, d;
    if (i < EE) {
        if (is64) {
            const long long* p = (const long long*)ei;
            s = (int)p[i];
            d = (int)p[EE + i];
        } else {
            const int* p = (const int*)ei;
            s = p[i];
            d = p[EE + i];
        }
    } else {
        s = i - EE;
        d = i - EE;
    }
    g_src[i] = s;
    g_dst[i] = d;
    atomicAdd(&g_cnt[d], 1);
}

// ---------------- decoupled scan: phase 1 (block sums) --------------------------
__global__ void __launch_bounds__(256) k_bsum() {
    int t = threadIdx.x, b = blockIdx.x;
    int i = b * 256 + t;
    int v = (i < NN) ? g_cnt[i] : 0;
    #pragma unroll
    for (int off = 16; off >= 1; off >>= 1)
        v += __shfl_xor_sync(0xffffffffu, v, off);
    __shared__ int ws[8];
    if ((t & 31) == 0) ws[t >> 5] = v;
    __syncthreads();
    if (t == 0) {
        int s = 0;
        #pragma unroll
        for (int w = 0; w < 8; w++) s += ws[w];
        g_bsum[b] = s;
    }
}

// ---------------- phase 2: exclusive scan of 200 block sums (1 block) -----------
__global__ void __launch_bounds__(256) k_bscan() {
    int t = threadIdx.x;
    int lane = t & 31, wid = t >> 5;
    int val = (t < SCAN_B) ? g_bsum[t] : 0;
    int v = val;
    #pragma unroll
    for (int off = 1; off < 32; off <<= 1) {
        int u = __shfl_up_sync(0xffffffffu, v, off);
        if (lane >= off) v += u;
    }
    __shared__ int ws[8];
    if (lane == 31) ws[wid] = v;
    __syncthreads();
    if (wid == 0) {
        int s = (lane < 8) ? ws[lane] : 0;
        #pragma unroll
        for (int off = 1; off < 8; off <<= 1) {
            int u = __shfl_up_sync(0xffffffffu, s, off);
            if (lane >= off) s += u;
        }
        if (lane < 8) ws[lane] = s;
    }
    __syncthreads();
    int base = (wid > 0) ? ws[wid - 1] : 0;
    g_boff[t] = base + v - val;   // exclusive
    if (t == 0) g_off[NN] = EA;
}

// ---------------- phase 3: local scan + global offset ---------------------------
__global__ void __launch_bounds__(256) k_offs() {
    int t = threadIdx.x, b = blockIdx.x;
    int i = b * 256 + t;
    int lane = t & 31, wid = t >> 5;
    int val = (i < NN) ? g_cnt[i] : 0;
    int v = val;
    #pragma unroll
    for (int off = 1; off < 32; off <<= 1) {
        int u = __shfl_up_sync(0xffffffffu, v, off);
        if (lane >= off) v += u;
    }
    __shared__ int ws[8];
    if (lane == 31) ws[wid] = v;
    __syncthreads();
    if (wid == 0) {
        int s = (lane < 8) ? ws[lane] : 0;
        #pragma unroll
        for (int off = 1; off < 8; off <<= 1) {
            int u = __shfl_up_sync(0xffffffffu, s, off);
            if (lane >= off) s += u;
        }
        if (lane < 8) ws[lane] = s;
    }
    __syncthreads();
    int base = ((wid > 0) ? ws[wid - 1] : 0) + g_boff[b];
    if (i < NN) {
        int excl = base + v - val;
        g_off[i] = excl;
        g_cur[i] = excl;
    }
}

// scatter + re-zero g_cnt for the next kernel_launch invocation
__global__ void k_scatter() {
    int i = blockIdx.x * blockDim.x + threadIdx.x;
    if (i < NN) g_cnt[i] = 0;
    if (i >= EA) return;
    int pos = atomicAdd(&g_cur[g_dst[i]], 1);
    g_csr[pos] = g_src[i];
}

// ---------------- GEMM: 64 nodes x 256 cols per block, 16n x 4c per thread ------
// shared holds h transposed [k][node]; warp reads are pure broadcast (N=1).
__global__ void __launch_bounds__(256, 2) k_gemm(const float* __restrict__ hin,
                                                 const float* __restrict__ Wl,
                                                 const float* __restrict__ Wr,
                                                 const float* __restrict__ bl,
                                                 const float* __restrict__ br) {
    __shared__ float sh[128][64];   // 32 KB, [k][node]
    int t = threadIdx.x;
    int nb = blockIdx.x * 64;
    const float4* hin4 = (const float4*)hin;
    #pragma unroll
    for (int r = 0; r < 8; r++) {
        int p = r * 256 + t;        // 0..2047
        int n = p & 63, k4 = p >> 6;
        int gn = nb + n;
        float4 v = make_float4(0.f, 0.f, 0.f, 0.f);
        if (gn < NN) v = hin4[(size_t)gn * 32 + k4];
        sh[k4 * 4 + 0][n] = v.x;    // lanes write stride-1 -> conflict-free
        sh[k4 * 4 + 1][n] = v.y;
        sh[k4 * 4 + 2][n] = v.z;
        sh[k4 * 4 + 3][n] = v.w;
    }
    __syncthreads();

    int cg = t & 63, ng = t >> 6;
    int n0 = ng * 16;
    bool left = (cg < 32);
    const float* W    = left ? Wl : Wr;
    const float* bias = left ? bl : br;
    float* outp       = left ? g_xl : g_xr;
    int c0 = (cg & 31) * 4;
    float4 bv = *(const float4*)(bias + c0);

    unsigned long long acc[8][4];
    #pragma unroll
    for (int p = 0; p < 8; p++)
        #pragma unroll
        for (int c = 0; c < 4; c++) acc[p][c] = 0ull;

    #pragma unroll 4
    for (int k = 0; k < 128; k++) {
        float4 w = *(const float4*)(W + k * 128 + c0);   // coalesced LDG.128
        unsigned long long wp[4];
        wp[0] = rep2(w.x); wp[1] = rep2(w.y); wp[2] = rep2(w.z); wp[3] = rep2(w.w);
        const ulonglong2* hp = (const ulonglong2*)(&sh[k][n0]);  // broadcast LDS.128
        ulonglong2 hA = hp[0], hB = hp[1], hC = hp[2], hD = hp[3];
        unsigned long long h[8] = {hA.x, hA.y, hB.x, hB.y, hC.x, hC.y, hD.x, hD.y};
        #pragma unroll
        for (int p = 0; p < 8; p++)
            #pragma unroll
            for (int c = 0; c < 4; c++)
                fma2(acc[p][c], h[p], wp[c]);
    }

    #pragma unroll
    for (int p = 0; p < 8; p++) {
        float2 v0 = unpack2(acc[p][0]);
        float2 v1 = unpack2(acc[p][1]);
        float2 v2 = unpack2(acc[p][2]);
        float2 v3 = unpack2(acc[p][3]);
        int ga = nb + n0 + p * 2;
        if (ga < NN) {
            float4 o = make_float4(v0.x + bv.x, v1.x + bv.y, v2.x + bv.z, v3.x + bv.w);
            *(float4*)(outp + (size_t)ga * 128 + c0) = o;
        }
        if (ga + 1 < NN) {
            float4 o = make_float4(v0.y + bv.x, v1.y + bv.y, v2.y + bv.z, v3.y + bv.w);
            *(float4*)(outp + (size_t)(ga + 1) * 128 + c0) = o;
        }
    }
}

// ---------------- fused edge pass: online softmax + aggregate + bias + relu -----
__global__ void __launch_bounds__(256) k_edge(const float* __restrict__ att,
                                              const float* __restrict__ cb,
                                              float* __restrict__ hnext) {
    int gid = blockIdx.x * blockDim.x + threadIdx.x;
    int n = gid >> 5, lane = gid & 31;
    if (n >= NN) return;
    const float4* xl4 = (const float4*)g_xl;
    float4 xr = ((const float4*)g_xr)[(size_t)n * 32 + lane];
    float4 w  = ((const float4*)att)[lane];
    int beg = g_off[n], end = g_off[n + 1];
    int cnt = end - beg;                   // >= 1 (self loop guaranteed)

    int   src0 = g_csr[beg];
    float4 an  = xl4[(size_t)src0 * 32 + lane];          // row for i=0
    int   idx1 = (cnt > 1) ? g_csr[beg + 1] : 0;         // idx for i=1

    float m = -1e30f, s = 0.f;
    float4 acc = make_float4(0.f, 0.f, 0.f, 0.f);

    for (int i = 0; i < cnt; i++) {
        float4 a = an;
        if (i + 1 < cnt) {
            an = xl4[(size_t)idx1 * 32 + lane];          // issue early
            idx1 = (i + 2 < cnt) ? g_csr[beg + i + 2] : 0;
        }
        float vx = a.x + xr.x, vy = a.y + xr.y, vz = a.z + xr.z, vw = a.w + xr.w;
        vx = fmaxf(vx, SLOPE * vx);
        vy = fmaxf(vy, SLOPE * vy);
        vz = fmaxf(vz, SLOPE * vz);
        vw = fmaxf(vw, SLOPE * vw);
        float p = vx * w.x + vy * w.y + vz * w.z + vw * w.w;
        p += __shfl_xor_sync(0xffffffffu, p, 1);
        p += __shfl_xor_sync(0xffffffffu, p, 2);
        p += __shfl_xor_sync(0xffffffffu, p, 4);
        float mn = fmaxf(m, p);
        float scale = __expf(m - mn);
        float t = __expf(p - mn);
        s = s * scale + t;
        acc.x = acc.x * scale + t * a.x;
        acc.y = acc.y * scale + t * a.y;
        acc.z = acc.z * scale + t * a.z;
        acc.w = acc.w * scale + t * a.w;
        m = mn;
    }
    float inv = __fdividef(1.f, s + 1e-16f);
    float4 cbv = ((const float4*)cb)[lane];
    float4 o;
    o.x = fmaxf(fmaf(acc.x, inv, cbv.x), 0.f);
    o.y = fmaxf(fmaf(acc.y, inv, cbv.y), 0.f);
    o.z = fmaxf(fmaf(acc.z, inv, cbv.z), 0.f);
    o.w = fmaxf(fmaf(acc.w, inv, cbv.w), 0.f);
    ((float4*)hnext)[(size_t)n * 32 + lane] = o;
}

// ---------------- fused MLP: relu(h@W1+b1) -> relu(@W2+b2) -> W3 partials -------
__global__ void __launch_bounds__(128) k_mlp(const float* __restrict__ hin,
                                             const float* __restrict__ W1,
                                             const float* __restrict__ b1,
                                             const float* __restrict__ W2,
                                             const float* __restrict__ b2,
                                             const float* __restrict__ W3) {
    __shared__ float4 sh[16][32];
    __shared__ float  s1[16][33];
    __shared__ float  s2[16][17];
    int t = threadIdx.x;
    int nb = blockIdx.x * 16;       // NN % 16 == 0
    const float4* hin4 = (const float4*)hin;
    #pragma unroll
    for (int r = 0; r < 4; r++) {
        int p = r * 128 + t;        // 0..511
        int n = p >> 5, k4 = p & 31;
        sh[n][k4] = hin4[(size_t)(nb + n) * 32 + k4];
    }
    __syncthreads();
    {
        int c = t & 31, n0 = t >> 5;
        #pragma unroll
        for (int rep = 0; rep < 4; rep++) {
            int n = n0 + rep * 4;
            float acc = b1[c];
            #pragma unroll 8
            for (int k4 = 0; k4 < 32; k4++) {
                float4 h = sh[n][k4];
                acc = fmaf(h.x, W1[(k4 * 4 + 0) * 32 + c], acc);
                acc = fmaf(h.y, W1[(k4 * 4 + 1) * 32 + c], acc);
                acc = fmaf(h.z, W1[(k4 * 4 + 2) * 32 + c], acc);
                acc = fmaf(h.w, W1[(k4 * 4 + 3) * 32 + c], acc);
            }
            s1[n][c] = fmaxf(acc, 0.f);
        }
    }
    __syncthreads();
    {
        int c = t & 15, n0 = t >> 4;
        #pragma unroll
        for (int rep = 0; rep < 2; rep++) {
            int n = n0 + rep * 8;
            float acc = b2[c];
            #pragma unroll
            for (int k = 0; k < 32; k++)
                acc = fmaf(s1[n][k], W2[k * 16 + c], acc);
            float v = fmaxf(acc, 0.f);
            s2[n][c] = v;
            g_mlp[(size_t)(nb + n) * 16 + c] = v;
        }
    }
    __syncthreads();
    if (t < 96) {
        int n = t / 6, c = t - (t / 6) * 6;
        float a1 = 0.f, a2 = 0.f;
        #pragma unroll
        for (int k = 0; k < 16; k++) {
            float v = s2[n][k];
            a1 = fmaf(v, W3[k * 6 + c], a1);
            a2 = fmaf(v, W3[(16 + k) * 6 + c], a2);
        }
        g_p1[(nb + n) * 6 + c] = a1;
        g_p2[(nb + n) * 6 + c] = a2;
    }
}

// ---------------- edge head: e = concat(h[src], h[dst]); out = p1+p2+b3 ---------
__global__ void __launch_bounds__(256) k_eout(const float* __restrict__ b3,
                                              float* __restrict__ outp,
                                              float* __restrict__ eoutp) {
    int gid = blockIdx.x * blockDim.x + threadIdx.x;
    int e = gid >> 5, lane = gid & 31;
    if (e >= EE) return;
    int s = g_src[e], d = g_dst[e];
    int node = (lane < 16) ? s : d;
    float v = g_mlp[(size_t)node * 16 + (lane & 15)];
    eoutp[(size_t)e * 32 + lane] = v;
    if (lane < 6) {
        float o = g_p1[s * 6 + lane] + g_p2[d * 6 + lane] + b3[lane];
        outp[(size_t)e * 6 + lane] = o;
    }
}

// ---------------- launch ---------------------------------------------------------
extern "C" void kernel_launch(void* const* d_in, const int* in_sizes, int n_in,
                              void* d_out, int out_size) {
    const float* x   = (const float*)d_in[0];
    const void*  ei  = d_in[1];
    // d_in[2] = batch (unused)
    const float* Wl  = (const float*)d_in[3];
    const float* Wr  = (const float*)d_in[4];
    const float* bl  = (const float*)d_in[5];
    const float* br  = (const float*)d_in[6];
    const float* att = (const float*)d_in[7];
    const float* cb  = (const float*)d_in[8];
    const float* W1  = (const float*)d_in[9];
    const float* b1  = (const float*)d_in[10];
    const float* W2  = (const float*)d_in[11];
    const float* b2  = (const float*)d_in[12];
    const float* W3  = (const float*)d_in[13];
    const float* b3  = (const float*)d_in[14];

    float* outp  = (float*)d_out;                   // [E, 6]
    float* eoutp = outp + (size_t)EE * 6;           // [E, 32]

    void* hsym = nullptr;
    cudaGetSymbolAddress(&hsym, g_h);
    float* hb0 = (float*)hsym;
    float* hb1 = hb0 + (size_t)NN * HC;

    // launch order: k_gemm (layer 0) deliberately placed 4th for ncu capture
    k_prep<<<cdiv(EA, 256), 256>>>(ei);                             // 1
    k_bsum<<<SCAN_B, 256>>>();                                      // 2
    k_bscan<<<1, 256>>>();                                          // 3
    k_gemm<<<cdiv(NN, 64), 256>>>(x, Wl, Wr, bl, br);               // 4 (profiled)
    k_offs<<<SCAN_B, 256>>>();                                      // 5
    k_scatter<<<cdiv(EA, 256), 256>>>();                            // 6

    float* hbuf[3] = {hb0, hb1, hb0};
    const float* hin = x;
    for (int i = 0; i < 3; i++) {
        float* hnext = hbuf[i];
        if (i > 0)
            k_gemm<<<cdiv(NN, 64), 256>>>(hin,
                                          Wl + (size_t)i * 128 * 128,
                                          Wr + (size_t)i * 128 * 128,
                                          bl + (size_t)i * 128,
                                          br + (size_t)i * 128);
        k_edge<<<cdiv(NN * 32, 256), 256>>>(att + (size_t)i * 128,
                                            cb + (size_t)i * 128, hnext);
        hin = hnext;
    }

    k_mlp<<<NN / 16, 128>>>(hin, W1, b1, W2, b2, W3);
    k_eout<<<cdiv(EE * 32, 256), 256>>>(b3, outp, eoutp);
}